// round 13
// baseline (speedup 1.0000x reference)
#include <cuda_runtime.h>
#include <cuda_bf16.h>
#include <cstdint>

// Problem constants
#define NTOK   10000
#define EMB    100
#define SEQT   80
#define UNITS  64
#define BATCH  8192
#define TILE_B 64
#define NBLK   (BATCH / TILE_B)   // 128
#define THREADS 256
#define EROWS  32

// Precomputed emb @ W1x + b1  (fp32 scratch)
__device__ float g_embW[NTOK * UNITS];

// ---------------- helpers ----------------
__device__ __forceinline__ uint32_t swz(uint32_t off) {           // SW128 swizzle
    return off ^ ((off >> 3) & 0x70);
}
__device__ __forceinline__ uint32_t smem_u32(const void* p) {
    uint32_t a;
    asm("{ .reg .u64 t; cvta.to.shared.u64 t, %1; cvt.u32.u64 %0, t; }" : "=r"(a) : "l"(p));
    return a;
}
__device__ __forceinline__ void ldsm4(uint32_t r[4], uint32_t addr) {
    asm volatile("ldmatrix.sync.aligned.m8n8.x4.shared.b16 {%0,%1,%2,%3}, [%4];"
                 : "=r"(r[0]), "=r"(r[1]), "=r"(r[2]), "=r"(r[3]) : "r"(addr));
}
__device__ __forceinline__ void ldsm4t(uint32_t r[4], uint32_t addr) {
    asm volatile("ldmatrix.sync.aligned.m8n8.x4.trans.shared.b16 {%0,%1,%2,%3}, [%4];"
                 : "=r"(r[0]), "=r"(r[1]), "=r"(r[2]), "=r"(r[3]) : "r"(addr));
}
__device__ __forceinline__ void mma16816(float c[4], const uint32_t a[4], const uint32_t b[2]) {
    asm volatile(
        "mma.sync.aligned.m16n8k16.row.col.f32.bf16.bf16.f32 "
        "{%0,%1,%2,%3}, {%4,%5,%6,%7}, {%8,%9}, {%0,%1,%2,%3};"
        : "+f"(c[0]), "+f"(c[1]), "+f"(c[2]), "+f"(c[3])
        : "r"(a[0]), "r"(a[1]), "r"(a[2]), "r"(a[3]), "r"(b[0]), "r"(b[1]));
}
__device__ __forceinline__ void sts32(uint32_t addr, uint32_t v) {
    asm volatile("st.shared.b32 [%0], %1;" :: "r"(addr), "r"(v) : "memory");
}
__device__ __forceinline__ void team_bar(int id) {
    asm volatile("bar.sync %0, 128;" :: "r"(id) : "memory");
}
__device__ __forceinline__ float tanha(float x) {
    float y;
    asm("tanh.approx.f32 %0, %1;" : "=f"(y) : "f"(x));
    return y;
}
__device__ __forceinline__ uint32_t pack_bf16x2(float lo, float hi) {
    uint32_t r;
    asm("cvt.rn.bf16x2.f32 %0, %1, %2;" : "=r"(r) : "f"(hi), "f"(lo));
    return r;
}
__device__ __forceinline__ uint32_t tanh_bf16x2(uint32_t x) {
    uint32_t y;
    asm("tanh.approx.bf16x2 %0, %1;" : "=r"(y) : "r"(x));
    return y;
}

// ---------- Kernel 1: embW[v][j] = sum_i emb[v][i] * W1x[i][j] + b1[j] ----------
// 32 rows/block; thread = (row 0..31, j-octet 0..7) -> 8 output cols.
__global__ void __launch_bounds__(256)
embw_kernel(const float* __restrict__ emb, const float* __restrict__ W1x,
            const float* __restrict__ b1) {
    __shared__ float sW[EMB * UNITS];    // 25.6 KB  [i][j]
    __shared__ float sE[EROWS * EMB];    // 12.8 KB
    int tid = threadIdx.x;
    for (int i = tid; i < EMB * UNITS; i += 256) sW[i] = W1x[i];
    int v0 = blockIdx.x * EROWS;
    int nrow = NTOK - v0; if (nrow > EROWS) nrow = EROWS;
    const float* esrc = emb + (long long)v0 * EMB;
    for (int i = tid; i < nrow * EMB; i += 256) sE[i] = esrc[i];   // coalesced
    __syncthreads();

    int row = tid >> 3;                  // 0..31
    int j0  = (tid & 7) << 3;            // 0,8,...,56
    int v   = v0 + row;
    if (v < NTOK) {
        float4 a0 = *(const float4*)(b1 + j0);
        float4 a1 = *(const float4*)(b1 + j0 + 4);
        const float* er = sE + row * EMB;
        #pragma unroll 5
        for (int i = 0; i < EMB; i++) {
            float e = er[i];
            const float* wr = sW + i * UNITS + j0;
            float4 w0 = *(const float4*)wr;
            float4 w1 = *(const float4*)(wr + 4);
            a0.x = fmaf(e, w0.x, a0.x); a0.y = fmaf(e, w0.y, a0.y);
            a0.z = fmaf(e, w0.z, a0.z); a0.w = fmaf(e, w0.w, a0.w);
            a1.x = fmaf(e, w1.x, a1.x); a1.y = fmaf(e, w1.y, a1.y);
            a1.z = fmaf(e, w1.z, a1.z); a1.w = fmaf(e, w1.w, a1.w);
        }
        float* dst = g_embW + (long long)v * UNITS + j0;
        *(float4*)dst = a0;
        *(float4*)(dst + 4) = a1;
    }
}

// ---------- Kernel 2: mma.sync RNN, two independent 4-warp teams ----------
// R8/R11 measured-best structure; epilogues use packed bf16x2 tanh (halved MUFU).
struct __align__(1024) Sm {
    __nv_bfloat16 w[3][4096];       // W1h, W2x, W2h as B = W[k][j], k-major, SW128
    __nv_bfloat16 h1[2][2048];      // per team: [32 rows][64 cols]
    __nv_bfloat16 h2[2][2048];
    float red[2][32];
};

__global__ void __launch_bounds__(THREADS)
rnn_kernel(const int* __restrict__ tokens,
           const float* __restrict__ W1h,
           const float* __restrict__ W2x,
           const float* __restrict__ W2h,
           const float* __restrict__ b2,
           const float* __restrict__ Wd,
           const float* __restrict__ bd,
           float* __restrict__ out) {
    __shared__ Sm sm;

    const int tid  = threadIdx.x;
    const int wid  = tid >> 5;
    const int lane = tid & 31;
    const int tm   = wid >> 2;             // team 0/1
    const int tw   = wid & 3;              // warp within team
    const int r0   = (tw & 1) * 16;        // warp's 16 rows within team tile
    const int c0w  = (tw >> 1) * 32;       // warp's 32 cols
    const int gid  = lane >> 2;
    const int cp   = lane & 3;
    const int row_lo = r0 + gid;           // team-local rows
    const int row_hi = row_lo + 8;
    const int bbase  = blockIdx.x * TILE_B + tm * 32;
    const int barid  = tm + 1;

    // ---- stage weights into shared (bf16, SW128 swizzled, k-major [k][j]) ----
    {
        const float* src[3] = {W1h, W2x, W2h};
        #pragma unroll
        for (int m = 0; m < 3; m++)
            for (int idx = tid; idx < UNITS * UNITS; idx += THREADS) {
                int k = idx >> 6, j = idx & 63;
                uint32_t sw = swz((uint32_t)(k * 128 + j * 2));
                *(__nv_bfloat16*)((char*)sm.w[m] + sw) = __float2bfloat16(src[m][idx]);
            }
    }
    __syncthreads();

    // ---- preload weight B-fragments into registers (loop-invariant) ----
    uint32_t w1b[4][4][2], w2xb[4][4][2], w2hb[4][4][2];
    {
        const uint32_t bw[3] = {smem_u32(sm.w[0]), smem_u32(sm.w[1]), smem_u32(sm.w[2])};
        #pragma unroll
        for (int kk = 0; kk < 4; kk++)
            #pragma unroll
            for (int np = 0; np < 2; np++) {
                uint32_t off = swz((uint32_t)((kk * 16 + (lane & 15)) * 128 +
                                              (c0w + np * 16 + (lane >> 4) * 8) * 2));
                uint32_t r[4];
                ldsm4t(r, bw[0] + off);
                w1b[kk][np*2][0] = r[0]; w1b[kk][np*2][1] = r[1];
                w1b[kk][np*2+1][0] = r[2]; w1b[kk][np*2+1][1] = r[3];
                ldsm4t(r, bw[1] + off);
                w2xb[kk][np*2][0] = r[0]; w2xb[kk][np*2][1] = r[1];
                w2xb[kk][np*2+1][0] = r[2]; w2xb[kk][np*2+1][1] = r[3];
                ldsm4t(r, bw[2] + off);
                w2hb[kk][np*2][0] = r[0]; w2hb[kk][np*2][1] = r[1];
                w2hb[kk][np*2+1][0] = r[2]; w2hb[kk][np*2+1][1] = r[3];
            }
    }

    // ---- loop-invariant addresses (team-local h tiles: 32 rows x 128 B) ----
    const uint32_t bh1 = smem_u32(sm.h1[tm]);
    const uint32_t bh2 = smem_u32(sm.h2[tm]);
    uint32_t aA1[4], aA2[4];
    #pragma unroll
    for (int kk = 0; kk < 4; kk++) {
        uint32_t off = swz((uint32_t)((r0 + (lane & 15)) * 128 + (kk * 2 + (lane >> 4)) * 16));
        aA1[kk] = bh1 + off;
        aA2[kk] = bh2 + off;
    }
    uint32_t st1l[4], st1h[4], st2l[4], st2h[4];
    int gcol[4];
    float2 b2p[4], wdp[4];
    #pragma unroll
    for (int j = 0; j < 4; j++) {
        int col = c0w + j * 8 + cp * 2;
        gcol[j] = col;
        uint32_t ol = swz((uint32_t)(row_lo * 128 + col * 2));
        uint32_t oh = swz((uint32_t)(row_hi * 128 + col * 2));
        st1l[j] = bh1 + ol; st1h[j] = bh1 + oh;
        st2l[j] = bh2 + ol; st2h[j] = bh2 + oh;
        b2p[j] = make_float2(b2[col], b2[col + 1]);
        wdp[j] = make_float2(Wd[col], Wd[col + 1]);
    }

    const int* tok_lo = tokens + (long long)(bbase + row_lo) * SEQT;
    const int* tok_hi = tokens + (long long)(bbase + row_hi) * SEQT;

    // ---- h-state A fragments (zero-initialized h(-1)) ----
    uint32_t A1f[4][4] = {}, A2f[4][4] = {};

    // ---- prefetch g(0) ----
    float2 gl[4], gh[4];
    {
        const float* pl = g_embW + (long long)tok_lo[0] * UNITS;
        const float* ph = g_embW + (long long)tok_hi[0] * UNITS;
        #pragma unroll
        for (int j = 0; j < 4; j++) {
            gl[j] = *(const float2*)(pl + gcol[j]);
            gh[j] = *(const float2*)(ph + gcol[j]);
        }
    }

    float p_lo = 0.0f, p_hi = 0.0f;

    #pragma unroll 1
    for (int t = 0; t < SEQT; t++) {
        // ---------- Phase 1: h1(t) = tanh(g(t) + h1(t-1) @ W1h) ----------
        float c[4][4];
        #pragma unroll
        for (int j = 0; j < 4; j++) {
            c[j][0] = gl[j].x; c[j][1] = gl[j].y;
            c[j][2] = gh[j].x; c[j][3] = gh[j].y;
        }
        #pragma unroll
        for (int kk = 0; kk < 4; kk++)
            #pragma unroll
            for (int j = 0; j < 4; j++)
                mma16816(c[j], A1f[kk], w1b[kk][j]);
        #pragma unroll
        for (int j = 0; j < 4; j++) {
            sts32(st1l[j], tanh_bf16x2(pack_bf16x2(c[j][0], c[j][1])));
            sts32(st1h[j], tanh_bf16x2(pack_bf16x2(c[j][2], c[j][3])));
        }
        team_bar(barid);

        // ---------- Phase 2: reload A1 = h1(t) ----------
        #pragma unroll
        for (int kk = 0; kk < 4; kk++) ldsm4(A1f[kk], aA1[kk]);

        // ---------- prefetch g(t+1) ----------
        if (t + 1 < SEQT) {
            const float* pl = g_embW + (long long)tok_lo[t + 1] * UNITS;
            const float* ph = g_embW + (long long)tok_hi[t + 1] * UNITS;
            #pragma unroll
            for (int j = 0; j < 4; j++) {
                gl[j] = *(const float2*)(pl + gcol[j]);
                gh[j] = *(const float2*)(ph + gcol[j]);
            }
        }

        // ---------- Phase 3: h2(t) = tanh(b2 + h1(t)@W2x + h2(t-1)@W2h) ----------
        #pragma unroll
        for (int j = 0; j < 4; j++) { c[j][0] = 0; c[j][1] = 0; c[j][2] = 0; c[j][3] = 0; }
        #pragma unroll
        for (int kk = 0; kk < 4; kk++)
            #pragma unroll
            for (int j = 0; j < 4; j++)
                mma16816(c[j], A1f[kk], w2xb[kk][j]);
        #pragma unroll
        for (int kk = 0; kk < 4; kk++)
            #pragma unroll
            for (int j = 0; j < 4; j++)
                mma16816(c[j], A2f[kk], w2hb[kk][j]);

        if (t < SEQT - 1) {
            #pragma unroll
            for (int j = 0; j < 4; j++) {
                sts32(st2l[j], tanh_bf16x2(pack_bf16x2(c[j][0] + b2p[j].x,
                                                       c[j][1] + b2p[j].y)));
                sts32(st2h[j], tanh_bf16x2(pack_bf16x2(c[j][2] + b2p[j].x,
                                                       c[j][3] + b2p[j].y)));
            }
            team_bar(barid);
            // ---------- Phase 4: reload A2 = h2(t) ----------
            #pragma unroll
            for (int kk = 0; kk < 4; kk++) ldsm4(A2f[kk], aA2[kk]);
        } else {
            // final step: fp32 tanh path feeding the dense output directly
            #pragma unroll
            for (int j = 0; j < 4; j++) {
                float t0 = tanha(c[j][0] + b2p[j].x);
                float t1 = tanha(c[j][1] + b2p[j].y);
                float t2 = tanha(c[j][2] + b2p[j].x);
                float t3 = tanha(c[j][3] + b2p[j].y);
                p_lo = fmaf(t0, wdp[j].x, fmaf(t1, wdp[j].y, p_lo));
                p_hi = fmaf(t2, wdp[j].x, fmaf(t3, wdp[j].y, p_hi));
            }
        }
    }

    // ---- reduce dense partials (atomic-free, per team) ----
    p_lo += __shfl_xor_sync(0xFFFFFFFF, p_lo, 1);
    p_lo += __shfl_xor_sync(0xFFFFFFFF, p_lo, 2);
    p_hi += __shfl_xor_sync(0xFFFFFFFF, p_hi, 1);
    p_hi += __shfl_xor_sync(0xFFFFFFFF, p_hi, 2);
    // Pass 1: col-half warps (tw 2-3, cols 32-63) store partials.
    if (tw >= 2 && cp == 0) {
        sm.red[tm][row_lo] = p_lo;
        sm.red[tm][row_hi] = p_hi;
    }
    team_bar(barid);
    // Pass 2: warps tw 0-1 add their partials and emit outputs.
    if (tw < 2 && cp == 0) {
        float zlo = p_lo + sm.red[tm][row_lo] + bd[0];
        float zhi = p_hi + sm.red[tm][row_hi] + bd[0];
        out[bbase + row_lo] = __fdividef(1.0f, 1.0f + __expf(-zlo));
        out[bbase + row_hi] = __fdividef(1.0f, 1.0f + __expf(-zhi));
    }
}

extern "C" void kernel_launch(void* const* d_in, const int* in_sizes, int n_in,
                              void* d_out, int out_size) {
    const int*   tokens = (const int*)  d_in[0];
    const float* emb    = (const float*)d_in[1];
    const float* W1x    = (const float*)d_in[2];
    const float* W1h    = (const float*)d_in[3];
    const float* b1     = (const float*)d_in[4];
    const float* W2x    = (const float*)d_in[5];
    const float* W2h    = (const float*)d_in[6];
    const float* b2     = (const float*)d_in[7];
    const float* Wd     = (const float*)d_in[8];
    const float* bd     = (const float*)d_in[9];

    embw_kernel<<<(NTOK + EROWS - 1) / EROWS, 256>>>(emb, W1x, b1);
    rnn_kernel<<<NBLK, THREADS>>>(tokens, W1h, W2x, W2h, b2, Wd, bd, (float*)d_out);
}

// round 16
// speedup vs baseline: 1.1828x; 1.1828x over previous
#include <cuda_runtime.h>
#include <cuda_bf16.h>
#include <cstdint>

// Problem constants
#define NTOK   10000
#define EMB    100
#define SEQT   80
#define UNITS  64
#define BATCH  8192
#define TILE_B 64
#define NBLK   (BATCH / TILE_B)   // 128
#define THREADS 256

// Precomputed emb @ W1x + b1  (fp32 scratch)
__device__ float g_embW[NTOK * UNITS];

// ---------------- helpers ----------------
__device__ __forceinline__ uint32_t swz(uint32_t off) {           // SW128 swizzle
    return off ^ ((off >> 3) & 0x70);
}
__device__ __forceinline__ uint32_t smem_u32(const void* p) {
    uint32_t a;
    asm("{ .reg .u64 t; cvta.to.shared.u64 t, %1; cvt.u32.u64 %0, t; }" : "=r"(a) : "l"(p));
    return a;
}
__device__ __forceinline__ void ldsm4(uint32_t r[4], uint32_t addr) {
    asm volatile("ldmatrix.sync.aligned.m8n8.x4.shared.b16 {%0,%1,%2,%3}, [%4];"
                 : "=r"(r[0]), "=r"(r[1]), "=r"(r[2]), "=r"(r[3]) : "r"(addr));
}
__device__ __forceinline__ void ldsm4t(uint32_t r[4], uint32_t addr) {
    asm volatile("ldmatrix.sync.aligned.m8n8.x4.trans.shared.b16 {%0,%1,%2,%3}, [%4];"
                 : "=r"(r[0]), "=r"(r[1]), "=r"(r[2]), "=r"(r[3]) : "r"(addr));
}
__device__ __forceinline__ void mma16816(float c[4], const uint32_t a[4], const uint32_t b[2]) {
    asm volatile(
        "mma.sync.aligned.m16n8k16.row.col.f32.bf16.bf16.f32 "
        "{%0,%1,%2,%3}, {%4,%5,%6,%7}, {%8,%9}, {%0,%1,%2,%3};"
        : "+f"(c[0]), "+f"(c[1]), "+f"(c[2]), "+f"(c[3])
        : "r"(a[0]), "r"(a[1]), "r"(a[2]), "r"(a[3]), "r"(b[0]), "r"(b[1]));
}
__device__ __forceinline__ void sts32(uint32_t addr, uint32_t v) {
    asm volatile("st.shared.b32 [%0], %1;" :: "r"(addr), "r"(v) : "memory");
}
__device__ __forceinline__ void pair_bar(int id) {
    asm volatile("bar.sync %0, 64;" :: "r"(id) : "memory");
}
__device__ __forceinline__ float tanha(float x) {
    float y;
    asm("tanh.approx.f32 %0, %1;" : "=f"(y) : "f"(x));
    return y;
}
__device__ __forceinline__ uint32_t pack_bf16x2(float lo, float hi) {
    uint32_t r;
    asm("cvt.rn.bf16x2.f32 %0, %1, %2;" : "=r"(r) : "f"(hi), "f"(lo));
    return r;
}

// ---------- Kernel 1: embW[v][j] = sum_i emb[v][i] * W1x[i][j] + b1[j] ----------
// (R11 measured-best: 16 rows/block, float4 weight loads, coalesced staging.)
__global__ void __launch_bounds__(256)
embw_kernel(const float* __restrict__ emb, const float* __restrict__ W1x,
            const float* __restrict__ b1) {
    __shared__ float sW[EMB * UNITS];   // 25.6 KB  [i][j]
    __shared__ float sE[16 * EMB];      // 6.4 KB
    int tid = threadIdx.x;
    for (int i = tid; i < EMB * UNITS; i += 256) sW[i] = W1x[i];
    int v0 = blockIdx.x * 16;
    const float* esrc = emb + (long long)v0 * EMB;
    for (int i = tid; i < 16 * EMB; i += 256) sE[i] = esrc[i];   // coalesced
    __syncthreads();

    int row = tid >> 4;                 // 0..15
    int j0  = (tid & 15) << 2;          // 0,4,...,60
    int v   = v0 + row;
    if (v < NTOK) {
        float4 acc = *(const float4*)(b1 + j0);
        const float* er = sE + row * EMB;
        #pragma unroll 10
        for (int i = 0; i < EMB; i++) {
            float e = er[i];
            float4 w = *(const float4*)(sW + i * UNITS + j0);
            acc.x = fmaf(e, w.x, acc.x);
            acc.y = fmaf(e, w.y, acc.y);
            acc.z = fmaf(e, w.z, acc.z);
            acc.w = fmaf(e, w.w, acc.w);
        }
        *(float4*)(g_embW + (long long)v * UNITS + j0) = acc;
    }
}

// ---------- Kernel 2: mma.sync RNN, four independent 2-warp pairs ----------
// R11 two-phase structure; barrier domain shrunk to the 64-thread pair
// (a warp + its column partner), 4 independent pipelines per block.
// Pair (tm, rg) = warps tm*4+rg (SMSP rg) and tm*4+2+rg (SMSP rg+2):
// each SMSP hosts 2 warps from different pairs.
struct __align__(1024) Sm {
    __nv_bfloat16 w[3][4096];       // W1h, W2x, W2h as B = W[k][j], k-major, SW128
    __nv_bfloat16 h1[4][1024];      // per pair: [16 rows][64 cols]
    __nv_bfloat16 h2[4][1024];
    float red[4][16];
};

__global__ void __launch_bounds__(THREADS)
rnn_kernel(const int* __restrict__ tokens,
           const float* __restrict__ W1h,
           const float* __restrict__ W2x,
           const float* __restrict__ W2h,
           const float* __restrict__ b2,
           const float* __restrict__ Wd,
           const float* __restrict__ bd,
           float* __restrict__ out) {
    __shared__ Sm sm;

    const int tid  = threadIdx.x;
    const int wid  = tid >> 5;
    const int lane = tid & 31;
    const int tm   = wid >> 2;             // 0/1
    const int tw   = wid & 3;
    const int rg   = tw & 1;               // rowgroup
    const int cg   = tw >> 1;              // colgroup
    const int pairid = tm * 2 + rg;        // 0..3
    const int barid  = pairid + 1;         // named barriers 1..4
    const int c0w  = cg * 32;              // warp's 32 cols
    const int gid  = lane >> 2;
    const int cp   = lane & 3;
    const int row_lo = gid;                // pair-local rows 0..7
    const int row_hi = gid + 8;            // 8..15
    const int bbase  = blockIdx.x * TILE_B + tm * 32 + rg * 16;

    // ---- stage weights into shared (bf16, SW128 swizzled, k-major [k][j]) ----
    {
        const float* src[3] = {W1h, W2x, W2h};
        #pragma unroll
        for (int m = 0; m < 3; m++)
            for (int idx = tid; idx < UNITS * UNITS; idx += THREADS) {
                int k = idx >> 6, j = idx & 63;
                uint32_t sw = swz((uint32_t)(k * 128 + j * 2));
                *(__nv_bfloat16*)((char*)sm.w[m] + sw) = __float2bfloat16(src[m][idx]);
            }
    }
    __syncthreads();

    // ---- preload weight B-fragments into registers (loop-invariant) ----
    uint32_t w1b[4][4][2], w2xb[4][4][2], w2hb[4][4][2];
    {
        const uint32_t bw[3] = {smem_u32(sm.w[0]), smem_u32(sm.w[1]), smem_u32(sm.w[2])};
        #pragma unroll
        for (int kk = 0; kk < 4; kk++)
            #pragma unroll
            for (int np = 0; np < 2; np++) {
                uint32_t off = swz((uint32_t)((kk * 16 + (lane & 15)) * 128 +
                                              (c0w + np * 16 + (lane >> 4) * 8) * 2));
                uint32_t r[4];
                ldsm4t(r, bw[0] + off);
                w1b[kk][np*2][0] = r[0]; w1b[kk][np*2][1] = r[1];
                w1b[kk][np*2+1][0] = r[2]; w1b[kk][np*2+1][1] = r[3];
                ldsm4t(r, bw[1] + off);
                w2xb[kk][np*2][0] = r[0]; w2xb[kk][np*2][1] = r[1];
                w2xb[kk][np*2+1][0] = r[2]; w2xb[kk][np*2+1][1] = r[3];
                ldsm4t(r, bw[2] + off);
                w2hb[kk][np*2][0] = r[0]; w2hb[kk][np*2][1] = r[1];
                w2hb[kk][np*2+1][0] = r[2]; w2hb[kk][np*2+1][1] = r[3];
            }
    }

    // ---- loop-invariant addresses (pair-local tile: 16 rows x 128 B) ----
    const uint32_t bh1 = smem_u32(sm.h1[pairid]);
    const uint32_t bh2 = smem_u32(sm.h2[pairid]);
    uint32_t aA1[4], aA2[4];
    #pragma unroll
    for (int kk = 0; kk < 4; kk++) {
        uint32_t off = swz((uint32_t)((lane & 15) * 128 + (kk * 2 + (lane >> 4)) * 16));
        aA1[kk] = bh1 + off;
        aA2[kk] = bh2 + off;
    }
    uint32_t st1l[4], st1h[4], st2l[4], st2h[4];
    int gcol[4];
    float2 b2p[4], wdp[4];
    #pragma unroll
    for (int j = 0; j < 4; j++) {
        int col = c0w + j * 8 + cp * 2;
        gcol[j] = col;
        uint32_t ol = swz((uint32_t)(row_lo * 128 + col * 2));
        uint32_t oh = swz((uint32_t)(row_hi * 128 + col * 2));
        st1l[j] = bh1 + ol; st1h[j] = bh1 + oh;
        st2l[j] = bh2 + ol; st2h[j] = bh2 + oh;
        b2p[j] = make_float2(b2[col], b2[col + 1]);
        wdp[j] = make_float2(Wd[col], Wd[col + 1]);
    }

    const int* tok_lo = tokens + (long long)(bbase + row_lo) * SEQT;
    const int* tok_hi = tokens + (long long)(bbase + row_hi) * SEQT;

    // ---- h-state A fragments (zero-initialized h(-1)) ----
    uint32_t A1f[4][4] = {}, A2f[4][4] = {};

    // ---- prefetch g(0) ----
    float2 gl[4], gh[4];
    {
        const float* pl = g_embW + (long long)tok_lo[0] * UNITS;
        const float* ph = g_embW + (long long)tok_hi[0] * UNITS;
        #pragma unroll
        for (int j = 0; j < 4; j++) {
            gl[j] = *(const float2*)(pl + gcol[j]);
            gh[j] = *(const float2*)(ph + gcol[j]);
        }
    }

    float p_lo = 0.0f, p_hi = 0.0f;

    #pragma unroll 1
    for (int t = 0; t < SEQT; t++) {
        // ---------- Phase 1: h1(t) = tanh(g(t) + h1(t-1) @ W1h) ----------
        float c[4][4];
        #pragma unroll
        for (int j = 0; j < 4; j++) {
            c[j][0] = gl[j].x; c[j][1] = gl[j].y;
            c[j][2] = gh[j].x; c[j][3] = gh[j].y;
        }
        #pragma unroll
        for (int kk = 0; kk < 4; kk++)
            #pragma unroll
            for (int j = 0; j < 4; j++)
                mma16816(c[j], A1f[kk], w1b[kk][j]);
        #pragma unroll
        for (int j = 0; j < 4; j++) {
            sts32(st1l[j], pack_bf16x2(tanha(c[j][0]), tanha(c[j][1])));
            sts32(st1h[j], pack_bf16x2(tanha(c[j][2]), tanha(c[j][3])));
        }
        pair_bar(barid);

        // ---------- Phase 2: reload A1 = h1(t) ----------
        #pragma unroll
        for (int kk = 0; kk < 4; kk++) ldsm4(A1f[kk], aA1[kk]);

        // ---------- prefetch g(t+1) ----------
        if (t + 1 < SEQT) {
            const float* pl = g_embW + (long long)tok_lo[t + 1] * UNITS;
            const float* ph = g_embW + (long long)tok_hi[t + 1] * UNITS;
            #pragma unroll
            for (int j = 0; j < 4; j++) {
                gl[j] = *(const float2*)(pl + gcol[j]);
                gh[j] = *(const float2*)(ph + gcol[j]);
            }
        }

        // ---------- Phase 3: h2(t) = tanh(b2 + h1(t)@W2x + h2(t-1)@W2h) ----------
        #pragma unroll
        for (int j = 0; j < 4; j++) { c[j][0] = 0; c[j][1] = 0; c[j][2] = 0; c[j][3] = 0; }
        #pragma unroll
        for (int kk = 0; kk < 4; kk++)
            #pragma unroll
            for (int j = 0; j < 4; j++)
                mma16816(c[j], A1f[kk], w2xb[kk][j]);
        #pragma unroll
        for (int kk = 0; kk < 4; kk++)
            #pragma unroll
            for (int j = 0; j < 4; j++)
                mma16816(c[j], A2f[kk], w2hb[kk][j]);

        if (t < SEQT - 1) {
            #pragma unroll
            for (int j = 0; j < 4; j++) {
                float t0 = tanha(c[j][0] + b2p[j].x);
                float t1 = tanha(c[j][1] + b2p[j].y);
                float t2 = tanha(c[j][2] + b2p[j].x);
                float t3 = tanha(c[j][3] + b2p[j].y);
                sts32(st2l[j], pack_bf16x2(t0, t1));
                sts32(st2h[j], pack_bf16x2(t2, t3));
            }
            pair_bar(barid);
            // ---------- Phase 4: reload A2 = h2(t) ----------
            #pragma unroll
            for (int kk = 0; kk < 4; kk++) ldsm4(A2f[kk], aA2[kk]);
        } else {
            // final step: dense partial from fp32 values directly
            #pragma unroll
            for (int j = 0; j < 4; j++) {
                float t0 = tanha(c[j][0] + b2p[j].x);
                float t1 = tanha(c[j][1] + b2p[j].y);
                float t2 = tanha(c[j][2] + b2p[j].x);
                float t3 = tanha(c[j][3] + b2p[j].y);
                p_lo = fmaf(t0, wdp[j].x, fmaf(t1, wdp[j].y, p_lo));
                p_hi = fmaf(t2, wdp[j].x, fmaf(t3, wdp[j].y, p_hi));
            }
        }
    }

    // ---- reduce dense partials (atomic-free, per pair) ----
    p_lo += __shfl_xor_sync(0xFFFFFFFF, p_lo, 1);
    p_lo += __shfl_xor_sync(0xFFFFFFFF, p_lo, 2);
    p_hi += __shfl_xor_sync(0xFFFFFFFF, p_hi, 1);
    p_hi += __shfl_xor_sync(0xFFFFFFFF, p_hi, 2);
    // Pass 1: colgroup-1 warp stores partials.
    if (cg == 1 && cp == 0) {
        sm.red[pairid][row_lo] = p_lo;
        sm.red[pairid][row_hi] = p_hi;
    }
    pair_bar(barid);
    // Pass 2: colgroup-0 warp adds and emits outputs.
    if (cg == 0 && cp == 0) {
        float zlo = p_lo + sm.red[pairid][row_lo] + bd[0];
        float zhi = p_hi + sm.red[pairid][row_hi] + bd[0];
        out[bbase + row_lo] = __fdividef(1.0f, 1.0f + __expf(-zlo));
        out[bbase + row_hi] = __fdividef(1.0f, 1.0f + __expf(-zhi));
    }
}

extern "C" void kernel_launch(void* const* d_in, const int* in_sizes, int n_in,
                              void* d_out, int out_size) {
    const int*   tokens = (const int*)  d_in[0];
    const float* emb    = (const float*)d_in[1];
    const float* W1x    = (const float*)d_in[2];
    const float* W1h    = (const float*)d_in[3];
    const float* b1     = (const float*)d_in[4];
    const float* W2x    = (const float*)d_in[5];
    const float* W2h    = (const float*)d_in[6];
    const float* b2     = (const float*)d_in[7];
    const float* Wd     = (const float*)d_in[8];
    const float* bd     = (const float*)d_in[9];

    embw_kernel<<<(NTOK + 15) / 16, 256>>>(emb, W1x, b1);
    rnn_kernel<<<NBLK, THREADS>>>(tokens, W1h, W2x, W2h, b2, Wd, bd, (float*)d_out);
}